// round 16
// baseline (speedup 1.0000x reference)
#include <cuda_runtime.h>
#include <math.h>

// ---------------------------------------------------------------------------
// AcousticGuitarPoC R16: fused (pre-LP + KS, y streamed to global via STG)
// -> bodyAB -> bodyC -> lpout (post-LP commuted past the LTI body to the
// mixed output). B=8, N=32768. 4 launches.
// ---------------------------------------------------------------------------

#define FS_F   44100.0f
#define PI_F   3.14159265358979323846f
#define NB     24
#define NSMP   32768
#define BATCH  8
#define NTH    256      // fused-kernel threads
#define LCH    128      // LP chunk length (256*128 = 32768)
#define KSL    1024     // KS ring (power of 2)
#define BL     128      // body chunk length
#define BC     256      // body chunk count (256*128 = 32768)
#define NLVL   8        // log2(BC) scan levels

#define SIDX(n) ((n) + ((n) >> 7))          // skewed signal index
#define SIGSZ   (NSMP + (NSMP >> 7))        // 33024 floats

__device__ float  d_bA1[NB], d_bA2[NB], d_bB0[NB];
__device__ float  d_A2[NB][4];                // A^2 per band (double-computed)
__device__ float  d_Pl[NB][NLVL][4];          // M^(BL*2^j), double-computed
__device__ float  d_scr[BATCH * NSMP];        // raw KS string (pre body)
__device__ float2 d_initS[BATCH][BC][NB];     // body corrected chunk init states
__device__ float2 d_post[BATCH];              // post-LP (m, sc) per batch

__device__ __forceinline__ float sigm(float x) { return 1.f / (1.f + expf(-x)); }
__device__ __forceinline__ float clampf(float x, float lo, float hi) {
    return fminf(fmaxf(x, lo), hi);
}

__device__ __forceinline__ void mlp_eval(float p,
    const float* __restrict__ w1, const float* __restrict__ b1,
    const float* __restrict__ w2, const float* __restrict__ b2,
    float& lc, float& lm, float& lp)
{
    float m0 = b2[0], m1 = b2[1], m2 = b2[2];
    #pragma unroll
    for (int j = 0; j < 16; j++) {
        float h = fmaxf(fmaf(p, w1[j], b1[j]), 0.f);
        m0 = fmaf(h, w2[j],      m0);
        m1 = fmaf(h, w2[16 + j], m1);
        m2 = fmaf(h, w2[32 + j], m2);
    }
    lc = clampf(m0, -2.0f, 2.5f);
    lm = clampf(m1, -2.5f, 0.0f);
    lp = clampf(m2, -4.0f, 4.0f);
}

// In-place one-pole LP on the SKEWED signal (proven R7 version).
__device__ void lp_inplace(float* sig, float* ws, float m, float sc, int tid)
{
    int lane = tid & 31, wid = tid >> 5;
    float* x = sig + tid * (LCH + 1);

    float e = 0.f;
    #pragma unroll 8
    for (int k = 0; k < LCH; k++) e = fmaf(m, e, sc * x[k]);

    float f128 = m;
    #pragma unroll
    for (int i = 0; i < 7; i++) f128 *= f128;

    float f = f128;
    #pragma unroll
    for (int ofs = 1; ofs < 32; ofs <<= 1) {
        float v = __shfl_up_sync(0xffffffffu, e, ofs);
        if (lane >= ofs) e = fmaf(f, v, e);
        f *= f;
    }

    if (lane == 31) ws[wid] = e;
    __syncthreads();
    if (wid == 0 && lane < 8) {
        float t = ws[lane];
        float g = f;
        #pragma unroll
        for (int ofs = 1; ofs < 8; ofs <<= 1) {
            float v = __shfl_up_sync(0x000000ffu, t, ofs);
            if (lane >= ofs) t = fmaf(g, v, t);
            g *= g;
        }
        ws[lane] = t;
    }
    __syncthreads();

    float carry = (wid > 0) ? ws[wid - 1] : 0.f;
    float lmul = exp2f((float)(lane + 1) * log2f(f128));
    float Y = fmaf(lmul, carry, e);
    float yp = __shfl_up_sync(0xffffffffu, Y, 1);
    if (lane == 0) yp = carry;
    if (tid == 0)  yp = 0.f;

    #pragma unroll 8
    for (int k = 0; k < LCH; k++) { yp = fmaf(m, yp, sc * x[k]); x[k] = yp; }
    __syncthreads();
}

// ---------------------------------------------------------------------------
// Strength-reduced KS serial loop. sig holds pristine pre-LP x (never
// written); feedback lives in the ring; y is streamed to global gout via STG
// (coalesced, no barrier-drain cost, no writeback hazards). Cb in {128,256}
// so skewed indices advance linearly. Guarded prologue covers negative-time
// FIR reads only. Ring safety: ages <= lag+8 <= 516 < 1024; intra-round read
// distance lag >= Cb and 1024-(lag+8) >= 508 >= Cb.
// ---------------------------------------------------------------------------
template<int NSER, int NFIR>
__device__ __forceinline__ void ks_run(const float* sig, float* buf,
    float* __restrict__ gout,
    const float* __restrict__ sser, const float* __restrict__ sfc,
    const int* __restrict__ sfo, int lag, int Cb, int tid)
{
    if (tid < Cb) {
        float cs[NSER];
        #pragma unroll
        for (int j = 0; j < NSER; j++) cs[j] = sser[j];
        float fc[NFIR > 0 ? NFIR : 1];
        int   ofir[NFIR > 0 ? NFIR : 1];
        int maxoff = 0;
        #pragma unroll
        for (int j = 0; j < NFIR; j++) {
            fc[j] = sfc[j];
            int off = sfo[j];
            if (off > maxoff) maxoff = off;
            int i0 = tid - off;                    // signed
            ofir[j] = i0 + (i0 >> 7);              // skewed (monotone in i0)
        }
        const int STEP = Cb + (Cb >> 7);
        const int s0   = tid + (tid >> 7);
        const int rounds = NSMP / Cb;              // exact (Cb | 32768)
        int prail = (NFIR > 0) ? (maxoff / Cb + 1) : 0;
        if (prail > rounds) prail = rounds;

        int bk = 0;                                // k*STEP (skewed base)
        int gi = tid;                              // global write index
        int pr = tid - lag + 4096;                 // ring index base
        int k = 0;

        // -------- guarded prologue --------
        for (; k < prail; k++) {
            float acc = sig[bk + s0];
            float a1s = 0.f, a2s = 0.f;
            #pragma unroll
            for (int j = 0; j < NFIR; j++) {
                int si = bk + ofir[j];
                float v = (si >= 0) ? sig[si] : 0.f;
                if (j % 3 == 0)      acc = fmaf(fc[j], v, acc);
                else if (j % 3 == 1) a1s = fmaf(fc[j], v, a1s);
                else                 a2s = fmaf(fc[j], v, a2s);
            }
            float r0 = 0.f, r1 = 0.f;
            #pragma unroll
            for (int j = 0; j < NSER; j++) {
                float v = buf[(pr - j) & (KSL - 1)];
                if (j % 2 == 0) r0 = fmaf(cs[j], v, r0);
                else            r1 = fmaf(cs[j], v, r1);
            }
            float y = (acc + (a1s + a2s)) + (r0 + r1);
            buf[(pr + lag) & (KSL - 1)] = y;
            gout[gi] = y;
            pr += Cb; bk += STEP; gi += Cb;
            asm volatile("bar.sync 1, %0;" :: "r"(Cb) : "memory");
        }

        // -------- unguarded main loop --------
        for (; k < rounds; k++) {
            float acc = sig[bk + s0];
            float a1s = 0.f, a2s = 0.f;
            #pragma unroll
            for (int j = 0; j < NFIR; j++) {
                float v = sig[bk + ofir[j]];
                if (j % 3 == 0)      acc = fmaf(fc[j], v, acc);
                else if (j % 3 == 1) a1s = fmaf(fc[j], v, a1s);
                else                 a2s = fmaf(fc[j], v, a2s);
            }
            float r0 = 0.f, r1 = 0.f;
            #pragma unroll
            for (int j = 0; j < NSER; j++) {
                float v = buf[(pr - j) & (KSL - 1)];
                if (j % 2 == 0) r0 = fmaf(cs[j], v, r0);
                else            r1 = fmaf(cs[j], v, r1);
            }
            float y = (acc + (a1s + a2s)) + (r0 + r1);
            buf[(pr + lag) & (KSL - 1)] = y;
            gout[gi] = y;
            pr += Cb; bk += STEP; gi += Cb;
            asm volatile("bar.sync 1, %0;" :: "r"(Cb) : "memory");
        }
    }
}

// ---------------------------------------------------------------------------
// Fused kernel: one block per batch. pre-LP + KS only.
// ---------------------------------------------------------------------------
__global__ void fused_kernel(const float* __restrict__ exc,
                             const float* __restrict__ pitch,
                             const float* __restrict__ w1,
                             const float* __restrict__ b1,
                             const float* __restrict__ w2,
                             const float* __restrict__ b2,
                             const float* __restrict__ egain,
                             float* out_tail, int write_scalars)
{
    extern __shared__ float sm[];
    float* sig  = sm;              // [SIGSZ] skewed (pre-LP'd x)
    float* buf  = sm + SIGSZ;      // [KSL] ring
    float* scan = buf + KSL;       // [NTH]

    __shared__ float s_mpre, s_scpre;
    __shared__ float s_ser[9], s_fc[15];
    __shared__ int   s_fo[15];
    __shared__ int   s_L, s_lag, s_Cb;
    __shared__ float s_lc[BATCH], s_lm[BATCH], s_lp[BATCH];

    int b = blockIdx.x, tid = threadIdx.x;

    if (tid == 0) {
        float p = pitch[b];
        float lc, lm, lp;
        mlp_eval(p, w1, b1, w2, b2, lc, lm, lp);

        float g = 0.999f * sigm(lc);
        float s = sigm(lm);
        float gs  = g * s;
        float g1s = g * (1.f - s);

        float f0    = fmaxf(p, 60.f);
        float mult  = clampf(2.f + 6.f * (f0 - 60.f) / 600.f, 2.f, 8.f);
        float cut   = fminf(2.f * PI_F * f0 * mult / FS_F, PI_F * 0.9f);
        float alpha = 1.f - expf(-cut);
        s_mpre  = 1.f - alpha;
        s_scpre = alpha * egain[0];

        float cutp = fminf(PI_F * sigm(lp), PI_F * 0.99f);
        float ap   = 1.f - expf(-cutp);
        d_post[b] = make_float2(1.f - ap, ap);   // post-LP for lpout kernel

        float D  = clampf(FS_F / f0, 2.f, 735.f);
        float Df = floorf(D);
        int   Di = (int)Df;
        float fr = D - Df;

        // taps: C, C^2, C^3, C^4 — proven algebra
        float t1[3], t2[5], t3[7], t4[9];
        t1[0] = g1s * (1.f - fr);
        t1[1] = g1s * fr + gs * (1.f - fr);
        t1[2] = gs * fr;
        for (int k = 0; k < 5; k++) t2[k] = 0.f;
        for (int i = 0; i < 3; i++)
            for (int j = 0; j < 3; j++) t2[i + j] = fmaf(t1[i], t1[j], t2[i + j]);
        for (int k = 0; k < 7; k++) t3[k] = 0.f;
        for (int i = 0; i < 3; i++)
            for (int j = 0; j < 5; j++) t3[i + j] = fmaf(t1[i], t2[j], t3[i + j]);
        for (int k = 0; k < 9; k++) t4[k] = 0.f;
        for (int i = 0; i < 5; i++)
            for (int j = 0; j < 5; j++) t4[i + j] = fmaf(t2[i], t2[j], t4[i + j]);

        for (int k = 0; k < 9;  k++) s_ser[k] = 0.f;
        for (int k = 0; k < 15; k++) { s_fc[k] = 0.f; s_fo[k] = 0; }

        // level select: Cb=256 everywhere except Di in [255,257]
        if (Di >= 258) {
            s_L = 0; s_Cb = 256; s_lag = Di;
            for (int k = 0; k < 3; k++) s_ser[k] = t1[k];
        } else if (Di >= 255) {
            s_L = 0; s_Cb = 128; s_lag = Di;
            for (int k = 0; k < 3; k++) s_ser[k] = t1[k];
        } else if (Di >= 128) {
            s_L = 1; s_Cb = 256; s_lag = 2 * Di;
            for (int k = 0; k < 5; k++) s_ser[k] = t2[k];
            for (int k = 0; k < 3; k++) { s_fc[k] = t1[k]; s_fo[k] = Di + k; }
        } else if (Di >= 86) {
            s_L = 3; s_Cb = 256; s_lag = 3 * Di;
            for (int k = 0; k < 7; k++) s_ser[k] = t3[k];
            for (int k = 0; k < 3; k++) { s_fc[k]     = t1[k]; s_fo[k]     = Di + k; }
            for (int k = 0; k < 5; k++) { s_fc[3 + k] = t2[k]; s_fo[3 + k] = 2 * Di + k; }
        } else {
            s_L = 4; s_Cb = 256; s_lag = 4 * Di;
            for (int k = 0; k < 9; k++) s_ser[k] = t4[k];
            int q = 0;
            for (int k = 0; k < 3; k++, q++) { s_fc[q] = t1[k]; s_fo[q] = Di + k; }
            for (int k = 0; k < 5; k++, q++) { s_fc[q] = t2[k]; s_fo[q] = 2 * Di + k; }
            for (int k = 0; k < 7; k++, q++) { s_fc[q] = t3[k]; s_fo[q] = 3 * Di + k; }
        }
    }

    if (b == 0) {
        if (tid >= 32 && tid < 32 + BATCH) {
            int bb = tid - 32;
            mlp_eval(pitch[bb], w1, b1, w2, b2, s_lc[bb], s_lm[bb], s_lp[bb]);
        }
        if (tid >= 64 && tid < 64 + NB) {
            int band = tid - 64;
            double fc  = 80.0 * exp(log(100.0) * (double)band / 23.0);
            float  fcf = (float)fc;
            float  w   = 2.f * PI_F * fcf / FS_F;
            float  r   = expf(-PI_F * fcf / (10.f * FS_F));
            float  a1  = -2.f * r * cosf(w);
            float  a2  = r * r;
            d_bA1[band] = a1; d_bA2[band] = a2; d_bB0[band] = 1.f - r;
            // A = [[-a1,-a2],[1,0]]; A^2 and level powers M^(128*2^j),
            // all in double (non-normal matrix powers cancel in float).
            double ma = -(double)a1, mb = -(double)a2, mc = 1.0, md = 0.0;
            {
                double na = ma * ma + mb * mc;
                double nb = ma * mb + mb * md;
                double nc = mc * ma + md * mc;
                double nd = mc * mb + md * md;
                d_A2[band][0] = (float)na; d_A2[band][1] = (float)nb;
                d_A2[band][2] = (float)nc; d_A2[band][3] = (float)nd;
            }
            for (int it = 0; it < 7; it++) {
                double na = ma * ma + mb * mc;
                double nb = ma * mb + mb * md;
                double nc = mc * ma + md * mc;
                double nd = mc * mb + md * md;
                ma = na; mb = nb; mc = nc; md = nd;
            }
            for (int j = 0; j < NLVL; j++) {
                d_Pl[band][j][0] = (float)ma; d_Pl[band][j][1] = (float)mb;
                d_Pl[band][j][2] = (float)mc; d_Pl[band][j][3] = (float)md;
                double na = ma * ma + mb * mc;
                double nb = ma * mb + mb * md;
                double nc = mc * ma + md * mc;
                double nd = mc * mb + md * md;
                ma = na; mb = nb; mc = nc; md = nd;
            }
        }
    }
    __syncthreads();

    if (b == 0 && tid == 0 && write_scalars) {
        float sc = 0.f, smm = 0.f, spp = 0.f;
        for (int i = 0; i < BATCH; i++) { sc += s_lc[i]; smm += s_lm[i]; spp += s_lp[i]; }
        out_tail[0] = sc  / (float)BATCH;
        out_tail[1] = smm / (float)BATCH;
        out_tail[2] = spp / (float)BATCH;
    }

    // load excitation (skewed) + zero KS ring
    const float* xin = exc + b * NSMP;
    for (int i = tid; i < NSMP; i += NTH) sig[SIDX(i)] = xin[i];
    for (int i = tid; i < KSL; i += NTH) buf[i] = 0.f;
    __syncthreads();

    // pre one-pole LP
    lp_inplace(sig, scan, s_mpre, s_scpre, tid);

    // Karplus-Strong; y streamed to d_scr
    {
        int lag = s_lag, Cb = s_Cb, L = s_L;
        float* gout = d_scr + b * NSMP;
        if (L == 0)      ks_run<3, 0>(sig, buf, gout, s_ser, s_fc, s_fo, lag, Cb, tid);
        else if (L == 1) ks_run<5, 3>(sig, buf, gout, s_ser, s_fc, s_fo, lag, Cb, tid);
        else if (L == 3) ks_run<7, 8>(sig, buf, gout, s_ser, s_fc, s_fo, lag, Cb, tid);
        else             ks_run<9, 15>(sig, buf, gout, s_ser, s_fc, s_fo, lag, Cb, tid);
    }
}

// ---------------------------------------------------------------------------
// bodyAB: block = (band, batch), 256 chunk-threads (R10/R11/R15 proven).
// ---------------------------------------------------------------------------
__global__ void bodyAB_kernel()
{
    extern __shared__ float sh[];            // [SIGSZ] skewed signal
    __shared__ float2 st[BC];
    int band = blockIdx.x, b = blockIdx.y, c = threadIdx.x;

    const float4* x4 = (const float4*)(d_scr + b * NSMP);
    for (int i4 = c; i4 < NSMP / 4; i4 += BC) {
        float4 v = x4[i4];
        int s = SIDX(i4 * 4);                // float4 never crosses a chunk
        sh[s] = v.x; sh[s + 1] = v.y; sh[s + 2] = v.z; sh[s + 3] = v.w;
    }
    __syncthreads();

    float a1 = d_bA1[band], b0 = d_bB0[band];
    float p00 = d_A2[band][0], p01 = d_A2[band][1];
    float p10 = d_A2[band][2], p11 = d_A2[band][3];
    const float* xs = sh + c * (BL + 1);     // skewed chunk base
    float sx = 0.f, sy = 0.f;                // (y[-1], y[-2]) = 0
    #pragma unroll 8
    for (int k = 0; k < BL / 2; k++) {
        float x0 = xs[2 * k], x1 = xs[2 * k + 1];
        float wx = b0 * fmaf(-a1, x0, x1);
        float wy = b0 * x0;
        float nx = fmaf(p00, sx, fmaf(p01, sy, wx));
        float ny = fmaf(p10, sx, fmaf(p11, sy, wy));
        sx = nx; sy = ny;
    }

    float2 v = make_float2(sx, sy);          // (y[127], y[126])
    st[c] = v;
    __syncthreads();
    #pragma unroll
    for (int j = 0; j < NLVL; j++) {
        int ofs = 1 << j;
        float q00 = d_Pl[band][j][0], q01 = d_Pl[band][j][1];
        float q10 = d_Pl[band][j][2], q11 = d_Pl[band][j][3];
        float2 pv = (c >= ofs) ? st[c - ofs] : make_float2(0.f, 0.f);
        __syncthreads();
        v.x = fmaf(q00, pv.x, fmaf(q01, pv.y, v.x));
        v.y = fmaf(q10, pv.x, fmaf(q11, pv.y, v.y));
        st[c] = v;
        __syncthreads();
    }
    d_initS[b][c][band] = (c > 0) ? st[c - 1] : make_float2(0.f, 0.f);
}

// ---------------------------------------------------------------------------
// Body pass C: A^2-doubled recompute, then weighted band sum (proven).
// ---------------------------------------------------------------------------
__global__ void bodyC_kernel(const float* __restrict__ gains, float* __restrict__ out)
{
    __shared__ float shx[BL];
    __shared__ float tile[BL * 25];   // [t][band], stride 25 (pad)
    __shared__ float shg[NB];
    int b = blockIdx.y, c = blockIdx.x, tid = threadIdx.x;
    const float* x = d_scr + b * NSMP + c * BL;
    for (int i = tid; i < BL; i += 32) shx[i] = x[i];
    if (tid < NB) shg[tid] = gains[tid];
    __syncthreads();

    if (tid < NB) {
        float a1 = d_bA1[tid], b0 = d_bB0[tid];
        float p00 = d_A2[tid][0], p01 = d_A2[tid][1];
        float p10 = d_A2[tid][2], p11 = d_A2[tid][3];
        float2 s = d_initS[b][c][tid];
        float sx = s.x, sy = s.y;            // (y[-1], y[-2])
        #pragma unroll 8
        for (int k = 0; k < BL / 2; k++) {
            float x0 = shx[2 * k], x1 = shx[2 * k + 1];
            float wx = b0 * fmaf(-a1, x0, x1);
            float wy = b0 * x0;
            float nx = fmaf(p00, sx, fmaf(p01, sy, wx));
            float ny = fmaf(p10, sx, fmaf(p11, sy, wy));
            tile[(2 * k)     * 25 + tid] = ny;   // y[2k]
            tile[(2 * k + 1) * 25 + tid] = nx;   // y[2k+1]
            sx = nx; sy = ny;
        }
    }
    __syncthreads();

    for (int t = tid; t < BL; t += 32) {
        float acc = 0.f;
        #pragma unroll
        for (int k = 0; k < NB; k++) acc = fmaf(tile[t * 25 + k], shg[k], acc);
        out[b * NSMP + c * BL + t] = acc;
    }
}

// ---------------------------------------------------------------------------
// lpout: post one-pole LP applied in place to the mixed output (LTI systems
// commute: body(LP(y)) == LP(body(y)), and the LP factors out of the band
// sum). One block per batch, proven lp_inplace on skewed smem staging.
// ---------------------------------------------------------------------------
__global__ void lpout_kernel(float* __restrict__ out)
{
    extern __shared__ float sm[];
    float* sig = sm;               // [SIGSZ]
    float* ws  = sm + SIGSZ;       // [NTH]
    int b = blockIdx.x, tid = threadIdx.x;

    float2 pp = d_post[b];         // (m, sc)
    float* o = out + b * NSMP;
    const float4* o4 = (const float4*)o;
    for (int i4 = tid; i4 < NSMP / 4; i4 += NTH) {
        float4 v = o4[i4];
        int s = SIDX(i4 * 4);
        sig[s] = v.x; sig[s + 1] = v.y; sig[s + 2] = v.z; sig[s + 3] = v.w;
    }
    __syncthreads();

    lp_inplace(sig, ws, pp.x, pp.y, tid);

    for (int i = tid; i < NSMP; i += NTH) o[i] = sig[SIDX(i)];
}

// ---------------------------------------------------------------------------
extern "C" void kernel_launch(void* const* d_in, const int* in_sizes, int n_in,
                              void* d_out, int out_size)
{
    const float* exc   = (const float*)d_in[0];   // [8,1,32768]
    const float* pitch = (const float*)d_in[1];   // [8,1]
    const float* w1    = (const float*)d_in[2];   // [16,1]
    const float* b1    = (const float*)d_in[3];   // [16]
    const float* w2    = (const float*)d_in[4];   // [3,16]
    const float* b2    = (const float*)d_in[5];   // [3]
    const float* eg    = (const float*)d_in[6];   // scalar
    const float* bg    = (const float*)d_in[7];   // [1,24]
    float* out = (float*)d_out;

    int wr = (out_size >= BATCH * NSMP + 3) ? 1 : 0;

    const int smem_fused = (SIGSZ + KSL + NTH) * (int)sizeof(float);  // ~137 KB
    const int smem_body  = SIGSZ * (int)sizeof(float);                // ~129 KB
    const int smem_lpout = (SIGSZ + NTH) * (int)sizeof(float);        // ~130 KB
    cudaFuncSetAttribute(fused_kernel,
                         cudaFuncAttributeMaxDynamicSharedMemorySize, smem_fused);
    cudaFuncSetAttribute(bodyAB_kernel,
                         cudaFuncAttributeMaxDynamicSharedMemorySize, smem_body);
    cudaFuncSetAttribute(lpout_kernel,
                         cudaFuncAttributeMaxDynamicSharedMemorySize, smem_lpout);

    fused_kernel<<<BATCH, NTH, smem_fused>>>(exc, pitch, w1, b1, w2, b2, eg,
                                             out + BATCH * NSMP, wr);
    bodyAB_kernel<<<dim3(NB, BATCH), BC, smem_body>>>();
    bodyC_kernel<<<dim3(BC, BATCH), 32>>>(bg, out);
    lpout_kernel<<<BATCH, NTH, smem_lpout>>>(out);
}

// round 17
// speedup vs baseline: 1.1528x; 1.1528x over previous
#include <cuda_runtime.h>
#include <math.h>

// ---------------------------------------------------------------------------
// AcousticGuitarPoC R17: fused (pre-LP + KS streamed to global via STG)
// -> bodyAB -> bodyC (mix -> d_mix) -> lpout2 (full-chip truncated-carry
// post-LP: m^256 <= 5.3e-7 so 512-sample windows are exact to fp32).
// B=8, N=32768. 4 launches.
// ---------------------------------------------------------------------------

#define FS_F   44100.0f
#define PI_F   3.14159265358979323846f
#define NB     24
#define NSMP   32768
#define BATCH  8
#define NTH    256      // fused-kernel threads
#define LCH    128      // LP chunk length (256*128 = 32768)
#define KSL    1024     // KS ring (power of 2)
#define BL     128      // body chunk length
#define BC     256      // body chunk count (256*128 = 32768)
#define NLVL   8        // log2(BC) scan levels
#define CH2    256      // lpout2 chunk length
#define NC2    128      // lpout2 chunk count

#define SIDX(n) ((n) + ((n) >> 7))          // skewed signal index
#define SIGSZ   (NSMP + (NSMP >> 7))        // 33024 floats

__device__ float  d_bA1[NB], d_bA2[NB], d_bB0[NB];
__device__ float  d_A2[NB][4];                // A^2 per band (double-computed)
__device__ float  d_Pl[NB][NLVL][4];          // M^(BL*2^j), double-computed
__device__ float  d_scr[BATCH * NSMP];        // raw KS string (pre body)
__device__ float  d_mix[BATCH * NSMP];        // body mix (pre post-LP)
__device__ float2 d_initS[BATCH][BC][NB];     // body corrected chunk init states
__device__ float2 d_post[BATCH];              // post-LP (m, sc) per batch

__device__ __forceinline__ float sigm(float x) { return 1.f / (1.f + expf(-x)); }
__device__ __forceinline__ float clampf(float x, float lo, float hi) {
    return fminf(fmaxf(x, lo), hi);
}

__device__ __forceinline__ void mlp_eval(float p,
    const float* __restrict__ w1, const float* __restrict__ b1,
    const float* __restrict__ w2, const float* __restrict__ b2,
    float& lc, float& lm, float& lp)
{
    float m0 = b2[0], m1 = b2[1], m2 = b2[2];
    #pragma unroll
    for (int j = 0; j < 16; j++) {
        float h = fmaxf(fmaf(p, w1[j], b1[j]), 0.f);
        m0 = fmaf(h, w2[j],      m0);
        m1 = fmaf(h, w2[16 + j], m1);
        m2 = fmaf(h, w2[32 + j], m2);
    }
    lc = clampf(m0, -2.0f, 2.5f);
    lm = clampf(m1, -2.5f, 0.0f);
    lp = clampf(m2, -4.0f, 4.0f);
}

// In-place one-pole LP on the SKEWED signal (proven R7 version).
__device__ void lp_inplace(float* sig, float* ws, float m, float sc, int tid)
{
    int lane = tid & 31, wid = tid >> 5;
    float* x = sig + tid * (LCH + 1);

    float e = 0.f;
    #pragma unroll 8
    for (int k = 0; k < LCH; k++) e = fmaf(m, e, sc * x[k]);

    float f128 = m;
    #pragma unroll
    for (int i = 0; i < 7; i++) f128 *= f128;

    float f = f128;
    #pragma unroll
    for (int ofs = 1; ofs < 32; ofs <<= 1) {
        float v = __shfl_up_sync(0xffffffffu, e, ofs);
        if (lane >= ofs) e = fmaf(f, v, e);
        f *= f;
    }

    if (lane == 31) ws[wid] = e;
    __syncthreads();
    if (wid == 0 && lane < 8) {
        float t = ws[lane];
        float g = f;
        #pragma unroll
        for (int ofs = 1; ofs < 8; ofs <<= 1) {
            float v = __shfl_up_sync(0x000000ffu, t, ofs);
            if (lane >= ofs) t = fmaf(g, v, t);
            g *= g;
        }
        ws[lane] = t;
    }
    __syncthreads();

    float carry = (wid > 0) ? ws[wid - 1] : 0.f;
    float lmul = exp2f((float)(lane + 1) * log2f(f128));
    float Y = fmaf(lmul, carry, e);
    float yp = __shfl_up_sync(0xffffffffu, Y, 1);
    if (lane == 0) yp = carry;
    if (tid == 0)  yp = 0.f;

    #pragma unroll 8
    for (int k = 0; k < LCH; k++) { yp = fmaf(m, yp, sc * x[k]); x[k] = yp; }
    __syncthreads();
}

// ---------------------------------------------------------------------------
// Strength-reduced KS serial loop (R16 proven). sig pristine; y streamed to
// global via STG (no barrier-drain, no writeback hazards). Cb in {128,256}.
// ---------------------------------------------------------------------------
template<int NSER, int NFIR>
__device__ __forceinline__ void ks_run(const float* sig, float* buf,
    float* __restrict__ gout,
    const float* __restrict__ sser, const float* __restrict__ sfc,
    const int* __restrict__ sfo, int lag, int Cb, int tid)
{
    if (tid < Cb) {
        float cs[NSER];
        #pragma unroll
        for (int j = 0; j < NSER; j++) cs[j] = sser[j];
        float fc[NFIR > 0 ? NFIR : 1];
        int   ofir[NFIR > 0 ? NFIR : 1];
        int maxoff = 0;
        #pragma unroll
        for (int j = 0; j < NFIR; j++) {
            fc[j] = sfc[j];
            int off = sfo[j];
            if (off > maxoff) maxoff = off;
            int i0 = tid - off;
            ofir[j] = i0 + (i0 >> 7);
        }
        const int STEP = Cb + (Cb >> 7);
        const int s0   = tid + (tid >> 7);
        const int rounds = NSMP / Cb;
        int prail = (NFIR > 0) ? (maxoff / Cb + 1) : 0;
        if (prail > rounds) prail = rounds;

        int bk = 0, gi = tid, pr = tid - lag + 4096;
        int k = 0;

        for (; k < prail; k++) {
            float acc = sig[bk + s0];
            float a1s = 0.f, a2s = 0.f;
            #pragma unroll
            for (int j = 0; j < NFIR; j++) {
                int si = bk + ofir[j];
                float v = (si >= 0) ? sig[si] : 0.f;
                if (j % 3 == 0)      acc = fmaf(fc[j], v, acc);
                else if (j % 3 == 1) a1s = fmaf(fc[j], v, a1s);
                else                 a2s = fmaf(fc[j], v, a2s);
            }
            float r0 = 0.f, r1 = 0.f;
            #pragma unroll
            for (int j = 0; j < NSER; j++) {
                float v = buf[(pr - j) & (KSL - 1)];
                if (j % 2 == 0) r0 = fmaf(cs[j], v, r0);
                else            r1 = fmaf(cs[j], v, r1);
            }
            float y = (acc + (a1s + a2s)) + (r0 + r1);
            buf[(pr + lag) & (KSL - 1)] = y;
            gout[gi] = y;
            pr += Cb; bk += STEP; gi += Cb;
            asm volatile("bar.sync 1, %0;" :: "r"(Cb) : "memory");
        }

        for (; k < rounds; k++) {
            float acc = sig[bk + s0];
            float a1s = 0.f, a2s = 0.f;
            #pragma unroll
            for (int j = 0; j < NFIR; j++) {
                float v = sig[bk + ofir[j]];
                if (j % 3 == 0)      acc = fmaf(fc[j], v, acc);
                else if (j % 3 == 1) a1s = fmaf(fc[j], v, a1s);
                else                 a2s = fmaf(fc[j], v, a2s);
            }
            float r0 = 0.f, r1 = 0.f;
            #pragma unroll
            for (int j = 0; j < NSER; j++) {
                float v = buf[(pr - j) & (KSL - 1)];
                if (j % 2 == 0) r0 = fmaf(cs[j], v, r0);
                else            r1 = fmaf(cs[j], v, r1);
            }
            float y = (acc + (a1s + a2s)) + (r0 + r1);
            buf[(pr + lag) & (KSL - 1)] = y;
            gout[gi] = y;
            pr += Cb; bk += STEP; gi += Cb;
            asm volatile("bar.sync 1, %0;" :: "r"(Cb) : "memory");
        }
    }
}

// ---------------------------------------------------------------------------
// Fused kernel: one block per batch. pre-LP + KS only (R16 proven).
// ---------------------------------------------------------------------------
__global__ void fused_kernel(const float* __restrict__ exc,
                             const float* __restrict__ pitch,
                             const float* __restrict__ w1,
                             const float* __restrict__ b1,
                             const float* __restrict__ w2,
                             const float* __restrict__ b2,
                             const float* __restrict__ egain,
                             float* out_tail, int write_scalars)
{
    extern __shared__ float sm[];
    float* sig  = sm;              // [SIGSZ] skewed (pre-LP'd x)
    float* buf  = sm + SIGSZ;      // [KSL] ring
    float* scan = buf + KSL;       // [NTH]

    __shared__ float s_mpre, s_scpre;
    __shared__ float s_ser[9], s_fc[15];
    __shared__ int   s_fo[15];
    __shared__ int   s_L, s_lag, s_Cb;
    __shared__ float s_lc[BATCH], s_lm[BATCH], s_lp[BATCH];

    int b = blockIdx.x, tid = threadIdx.x;

    if (tid == 0) {
        float p = pitch[b];
        float lc, lm, lp;
        mlp_eval(p, w1, b1, w2, b2, lc, lm, lp);

        float g = 0.999f * sigm(lc);
        float s = sigm(lm);
        float gs  = g * s;
        float g1s = g * (1.f - s);

        float f0    = fmaxf(p, 60.f);
        float mult  = clampf(2.f + 6.f * (f0 - 60.f) / 600.f, 2.f, 8.f);
        float cut   = fminf(2.f * PI_F * f0 * mult / FS_F, PI_F * 0.9f);
        float alpha = 1.f - expf(-cut);
        s_mpre  = 1.f - alpha;
        s_scpre = alpha * egain[0];

        float cutp = fminf(PI_F * sigm(lp), PI_F * 0.99f);
        float ap   = 1.f - expf(-cutp);
        d_post[b] = make_float2(1.f - ap, ap);

        float D  = clampf(FS_F / f0, 2.f, 735.f);
        float Df = floorf(D);
        int   Di = (int)Df;
        float fr = D - Df;

        float t1[3], t2[5], t3[7], t4[9];
        t1[0] = g1s * (1.f - fr);
        t1[1] = g1s * fr + gs * (1.f - fr);
        t1[2] = gs * fr;
        for (int k = 0; k < 5; k++) t2[k] = 0.f;
        for (int i = 0; i < 3; i++)
            for (int j = 0; j < 3; j++) t2[i + j] = fmaf(t1[i], t1[j], t2[i + j]);
        for (int k = 0; k < 7; k++) t3[k] = 0.f;
        for (int i = 0; i < 3; i++)
            for (int j = 0; j < 5; j++) t3[i + j] = fmaf(t1[i], t2[j], t3[i + j]);
        for (int k = 0; k < 9; k++) t4[k] = 0.f;
        for (int i = 0; i < 5; i++)
            for (int j = 0; j < 5; j++) t4[i + j] = fmaf(t2[i], t2[j], t4[i + j]);

        for (int k = 0; k < 9;  k++) s_ser[k] = 0.f;
        for (int k = 0; k < 15; k++) { s_fc[k] = 0.f; s_fo[k] = 0; }

        if (Di >= 258) {
            s_L = 0; s_Cb = 256; s_lag = Di;
            for (int k = 0; k < 3; k++) s_ser[k] = t1[k];
        } else if (Di >= 255) {
            s_L = 0; s_Cb = 128; s_lag = Di;
            for (int k = 0; k < 3; k++) s_ser[k] = t1[k];
        } else if (Di >= 128) {
            s_L = 1; s_Cb = 256; s_lag = 2 * Di;
            for (int k = 0; k < 5; k++) s_ser[k] = t2[k];
            for (int k = 0; k < 3; k++) { s_fc[k] = t1[k]; s_fo[k] = Di + k; }
        } else if (Di >= 86) {
            s_L = 3; s_Cb = 256; s_lag = 3 * Di;
            for (int k = 0; k < 7; k++) s_ser[k] = t3[k];
            for (int k = 0; k < 3; k++) { s_fc[k]     = t1[k]; s_fo[k]     = Di + k; }
            for (int k = 0; k < 5; k++) { s_fc[3 + k] = t2[k]; s_fo[3 + k] = 2 * Di + k; }
        } else {
            s_L = 4; s_Cb = 256; s_lag = 4 * Di;
            for (int k = 0; k < 9; k++) s_ser[k] = t4[k];
            int q = 0;
            for (int k = 0; k < 3; k++, q++) { s_fc[q] = t1[k]; s_fo[q] = Di + k; }
            for (int k = 0; k < 5; k++, q++) { s_fc[q] = t2[k]; s_fo[q] = 2 * Di + k; }
            for (int k = 0; k < 7; k++, q++) { s_fc[q] = t3[k]; s_fo[q] = 3 * Di + k; }
        }
    }

    if (b == 0) {
        if (tid >= 32 && tid < 32 + BATCH) {
            int bb = tid - 32;
            mlp_eval(pitch[bb], w1, b1, w2, b2, s_lc[bb], s_lm[bb], s_lp[bb]);
        }
        if (tid >= 64 && tid < 64 + NB) {
            int band = tid - 64;
            double fc  = 80.0 * exp(log(100.0) * (double)band / 23.0);
            float  fcf = (float)fc;
            float  w   = 2.f * PI_F * fcf / FS_F;
            float  r   = expf(-PI_F * fcf / (10.f * FS_F));
            float  a1  = -2.f * r * cosf(w);
            float  a2  = r * r;
            d_bA1[band] = a1; d_bA2[band] = a2; d_bB0[band] = 1.f - r;
            double ma = -(double)a1, mb = -(double)a2, mc = 1.0, md = 0.0;
            {
                double na = ma * ma + mb * mc;
                double nb = ma * mb + mb * md;
                double nc = mc * ma + md * mc;
                double nd = mc * mb + md * md;
                d_A2[band][0] = (float)na; d_A2[band][1] = (float)nb;
                d_A2[band][2] = (float)nc; d_A2[band][3] = (float)nd;
            }
            for (int it = 0; it < 7; it++) {
                double na = ma * ma + mb * mc;
                double nb = ma * mb + mb * md;
                double nc = mc * ma + md * mc;
                double nd = mc * mb + md * md;
                ma = na; mb = nb; mc = nc; md = nd;
            }
            for (int j = 0; j < NLVL; j++) {
                d_Pl[band][j][0] = (float)ma; d_Pl[band][j][1] = (float)mb;
                d_Pl[band][j][2] = (float)mc; d_Pl[band][j][3] = (float)md;
                double na = ma * ma + mb * mc;
                double nb = ma * mb + mb * md;
                double nc = mc * ma + md * mc;
                double nd = mc * mb + md * md;
                ma = na; mb = nb; mc = nc; md = nd;
            }
        }
    }
    __syncthreads();

    if (b == 0 && tid == 0 && write_scalars) {
        float sc = 0.f, smm = 0.f, spp = 0.f;
        for (int i = 0; i < BATCH; i++) { sc += s_lc[i]; smm += s_lm[i]; spp += s_lp[i]; }
        out_tail[0] = sc  / (float)BATCH;
        out_tail[1] = smm / (float)BATCH;
        out_tail[2] = spp / (float)BATCH;
    }

    const float* xin = exc + b * NSMP;
    for (int i = tid; i < NSMP; i += NTH) sig[SIDX(i)] = xin[i];
    for (int i = tid; i < KSL; i += NTH) buf[i] = 0.f;
    __syncthreads();

    lp_inplace(sig, scan, s_mpre, s_scpre, tid);

    {
        int lag = s_lag, Cb = s_Cb, L = s_L;
        float* gout = d_scr + b * NSMP;
        if (L == 0)      ks_run<3, 0>(sig, buf, gout, s_ser, s_fc, s_fo, lag, Cb, tid);
        else if (L == 1) ks_run<5, 3>(sig, buf, gout, s_ser, s_fc, s_fo, lag, Cb, tid);
        else if (L == 3) ks_run<7, 8>(sig, buf, gout, s_ser, s_fc, s_fo, lag, Cb, tid);
        else             ks_run<9, 15>(sig, buf, gout, s_ser, s_fc, s_fo, lag, Cb, tid);
    }
}

// ---------------------------------------------------------------------------
// bodyAB: block = (band, batch), 256 chunk-threads (proven).
// ---------------------------------------------------------------------------
__global__ void bodyAB_kernel()
{
    extern __shared__ float sh[];            // [SIGSZ] skewed signal
    __shared__ float2 st[BC];
    int band = blockIdx.x, b = blockIdx.y, c = threadIdx.x;

    const float4* x4 = (const float4*)(d_scr + b * NSMP);
    for (int i4 = c; i4 < NSMP / 4; i4 += BC) {
        float4 v = x4[i4];
        int s = SIDX(i4 * 4);
        sh[s] = v.x; sh[s + 1] = v.y; sh[s + 2] = v.z; sh[s + 3] = v.w;
    }
    __syncthreads();

    float a1 = d_bA1[band], b0 = d_bB0[band];
    float p00 = d_A2[band][0], p01 = d_A2[band][1];
    float p10 = d_A2[band][2], p11 = d_A2[band][3];
    const float* xs = sh + c * (BL + 1);
    float sx = 0.f, sy = 0.f;
    #pragma unroll 8
    for (int k = 0; k < BL / 2; k++) {
        float x0 = xs[2 * k], x1 = xs[2 * k + 1];
        float wx = b0 * fmaf(-a1, x0, x1);
        float wy = b0 * x0;
        float nx = fmaf(p00, sx, fmaf(p01, sy, wx));
        float ny = fmaf(p10, sx, fmaf(p11, sy, wy));
        sx = nx; sy = ny;
    }

    float2 v = make_float2(sx, sy);
    st[c] = v;
    __syncthreads();
    #pragma unroll
    for (int j = 0; j < NLVL; j++) {
        int ofs = 1 << j;
        float q00 = d_Pl[band][j][0], q01 = d_Pl[band][j][1];
        float q10 = d_Pl[band][j][2], q11 = d_Pl[band][j][3];
        float2 pv = (c >= ofs) ? st[c - ofs] : make_float2(0.f, 0.f);
        __syncthreads();
        v.x = fmaf(q00, pv.x, fmaf(q01, pv.y, v.x));
        v.y = fmaf(q10, pv.x, fmaf(q11, pv.y, v.y));
        st[c] = v;
        __syncthreads();
    }
    d_initS[b][c][band] = (c > 0) ? st[c - 1] : make_float2(0.f, 0.f);
}

// ---------------------------------------------------------------------------
// Body pass C: A^2-doubled recompute + weighted band sum -> d_mix.
// ---------------------------------------------------------------------------
__global__ void bodyC_kernel(const float* __restrict__ gains)
{
    __shared__ float shx[BL];
    __shared__ float tile[BL * 25];
    __shared__ float shg[NB];
    int b = blockIdx.y, c = blockIdx.x, tid = threadIdx.x;
    const float* x = d_scr + b * NSMP + c * BL;
    for (int i = tid; i < BL; i += 32) shx[i] = x[i];
    if (tid < NB) shg[tid] = gains[tid];
    __syncthreads();

    if (tid < NB) {
        float a1 = d_bA1[tid], b0 = d_bB0[tid];
        float p00 = d_A2[tid][0], p01 = d_A2[tid][1];
        float p10 = d_A2[tid][2], p11 = d_A2[tid][3];
        float2 s = d_initS[b][c][tid];
        float sx = s.x, sy = s.y;
        #pragma unroll 8
        for (int k = 0; k < BL / 2; k++) {
            float x0 = shx[2 * k], x1 = shx[2 * k + 1];
            float wx = b0 * fmaf(-a1, x0, x1);
            float wy = b0 * x0;
            float nx = fmaf(p00, sx, fmaf(p01, sy, wx));
            float ny = fmaf(p10, sx, fmaf(p11, sy, wy));
            tile[(2 * k)     * 25 + tid] = ny;
            tile[(2 * k + 1) * 25 + tid] = nx;
            sx = nx; sy = ny;
        }
    }
    __syncthreads();

    for (int t = tid; t < BL; t += 32) {
        float acc = 0.f;
        #pragma unroll
        for (int k = 0; k < NB; k++) acc = fmaf(tile[t * 25 + k], shg[k], acc);
        d_mix[b * NSMP + c * BL + t] = acc;
    }
}

// ---------------------------------------------------------------------------
// lpout2: post one-pole LP with truncated carry. Block = (chunk, batch),
// 1 warp. Window = [c*256-256, c*256+256): exact affine scan over the window,
// write only the second half. Carry older than 256 samples is < m^256 <=
// 5.3e-7 relative (m <= 0.9451 since loop_post is clipped to [-4,4]).
// ---------------------------------------------------------------------------
__global__ void lpout2_kernel(float* __restrict__ out)
{
    int c = blockIdx.x, b = blockIdx.y, t = threadIdx.x;
    float2 pp = d_post[b];
    float m = pp.x, sc = pp.y;
    const float* x = d_mix + b * NSMP;

    int n0 = c * CH2 - 256 + t * 16;
    float xs[16];
    #pragma unroll
    for (int j = 0; j < 16; j++) {
        int n = n0 + j;
        xs[j] = (n >= 0) ? x[n] : 0.f;
    }
    float e = 0.f;
    #pragma unroll
    for (int j = 0; j < 16; j++) e = fmaf(m, e, sc * xs[j]);

    float f = m;
    #pragma unroll
    for (int i = 0; i < 4; i++) f *= f;      // m^16

    #pragma unroll
    for (int ofs = 1; ofs < 32; ofs <<= 1) {
        float v = __shfl_up_sync(0xffffffffu, e, ofs);
        if (t >= ofs) e = fmaf(f, v, e);
        f *= f;
    }

    float init = __shfl_up_sync(0xffffffffu, e, 1);   // inclusive of t-1
    if (t == 0) init = 0.f;

    if (t >= 16) {                                    // second half = own chunk
        float yp = init;
        float* o = out + b * NSMP;
        #pragma unroll
        for (int j = 0; j < 16; j++) {
            yp = fmaf(m, yp, sc * xs[j]);
            o[n0 + j] = yp;
        }
    }
}

// ---------------------------------------------------------------------------
extern "C" void kernel_launch(void* const* d_in, const int* in_sizes, int n_in,
                              void* d_out, int out_size)
{
    const float* exc   = (const float*)d_in[0];   // [8,1,32768]
    const float* pitch = (const float*)d_in[1];   // [8,1]
    const float* w1    = (const float*)d_in[2];   // [16,1]
    const float* b1    = (const float*)d_in[3];   // [16]
    const float* w2    = (const float*)d_in[4];   // [3,16]
    const float* b2    = (const float*)d_in[5];   // [3]
    const float* eg    = (const float*)d_in[6];   // scalar
    const float* bg    = (const float*)d_in[7];   // [1,24]
    float* out = (float*)d_out;

    int wr = (out_size >= BATCH * NSMP + 3) ? 1 : 0;

    const int smem_fused = (SIGSZ + KSL + NTH) * (int)sizeof(float);  // ~137 KB
    const int smem_body  = SIGSZ * (int)sizeof(float);                // ~129 KB
    cudaFuncSetAttribute(fused_kernel,
                         cudaFuncAttributeMaxDynamicSharedMemorySize, smem_fused);
    cudaFuncSetAttribute(bodyAB_kernel,
                         cudaFuncAttributeMaxDynamicSharedMemorySize, smem_body);

    fused_kernel<<<BATCH, NTH, smem_fused>>>(exc, pitch, w1, b1, w2, b2, eg,
                                             out + BATCH * NSMP, wr);
    bodyAB_kernel<<<dim3(NB, BATCH), BC, smem_body>>>();
    bodyC_kernel<<<dim3(BC, BATCH), 32>>>(bg);
    lpout2_kernel<<<dim3(NC2, BATCH), 32>>>(out);
}